// round 4
// baseline (speedup 1.0000x reference)
#include <cuda_runtime.h>
#include <cuda_bf16.h>

// SpatialBlock: x[16,256,128,128] fp32
//   max_c(x), mean_c(x) -> conv7x7 (2->1, SAME zero pad) + bias -> hsigmoid -> x * gate
//
// R4: wave-balance both kernels at ~1024 blocks (6.92/SM, 1.2% tail vs 15.6%
//     at 512 blocks), streaming cache hints on the single-use 804 MB.
// K1: 1024 blocks x 64 thr, per-thread 256-channel max+sum of one float4 pixel.
// K2: 16x16 tile, 256 thr = 4 channel-quarters x 64 px4; conv gate in smem.

#define Bn 16
#define Cn 256
#define Hn 128
#define Wn 128
#define HWn (Hn * Wn)

__device__ float g_max[Bn * HWn];
__device__ float g_avg[Bn * HWn];

__global__ void __launch_bounds__(64)
reduce_kernel(const float* __restrict__ x) {
    int t = blockIdx.x * 64 + threadIdx.x;        // 0 .. B*HW/4 - 1
    int b = t / (HWn / 4);
    int p4 = t - b * (HWn / 4);

    const float4* xb = reinterpret_cast<const float4*>(x) +
                       (size_t)b * Cn * (HWn / 4) + p4;

    float4 v = __ldcs(xb);
    float4 mx = v;
    float4 sm = v;

#pragma unroll 16
    for (int c = 1; c < Cn; c++) {
        float4 u = __ldcs(xb + (size_t)c * (HWn / 4));
        mx.x = fmaxf(mx.x, u.x); mx.y = fmaxf(mx.y, u.y);
        mx.z = fmaxf(mx.z, u.z); mx.w = fmaxf(mx.w, u.w);
        sm.x += u.x; sm.y += u.y; sm.z += u.z; sm.w += u.w;
    }

    const float inv = 1.0f / (float)Cn;
    sm.x *= inv; sm.y *= inv; sm.z *= inv; sm.w *= inv;

    reinterpret_cast<float4*>(g_max)[(size_t)b * (HWn / 4) + p4] = mx;
    reinterpret_cast<float4*>(g_avg)[(size_t)b * (HWn / 4) + p4] = sm;
}

#define TW 16   // tile width  (pixels)
#define TH 16   // tile height (pixels)

__global__ void __launch_bounds__(256)
gate_mul_kernel(const float* __restrict__ x,
                const float* __restrict__ cw,   // [1,2,7,7] = 98 floats
                const float* __restrict__ cb,   // [1]
                float* __restrict__ out) {
    __shared__ float sw[98];
    __shared__ float sbias;
    __shared__ __align__(16) float smax[TH + 6][TW + 6];
    __shared__ __align__(16) float savg[TH + 6][TW + 6];
    __shared__ __align__(16) float sgate[TH][TW];

    int tid = threadIdx.x;                        // 0..255
    if (tid < 98) sw[tid] = cw[tid];
    if (tid == 98) sbias = cb[0];

    int b  = blockIdx.z;
    int h0 = blockIdx.y * TH;
    int w0 = blockIdx.x * TW;

    const float* bmax = g_max + b * HWn;
    const float* bavg = g_avg + b * HWn;

    // Cooperative halo load (zero padding == conv SAME zero-pad). 484 elems.
    for (int i = tid; i < (TH + 6) * (TW + 6); i += 256) {
        int r  = i / (TW + 6);
        int cc = i - r * (TW + 6);
        int hh = h0 + r - 3;
        int ww = w0 + cc - 3;
        float vm = 0.0f, va = 0.0f;
        if ((unsigned)hh < (unsigned)Hn && (unsigned)ww < (unsigned)Wn) {
            int gi = hh * Wn + ww;
            vm = bmax[gi];
            va = bavg[gi];
        }
        smax[r][cc] = vm;
        savg[r][cc] = va;
    }
    __syncthreads();

    // Conv + hsigmoid: each thread computes one pixel of the 16x16 tile
    {
        int r  = tid >> 4;         // 0..15
        int cp = tid & 15;         // 0..15
        float a0 = sbias;
#pragma unroll
        for (int ky = 0; ky < 7; ky++) {
#pragma unroll
            for (int kx = 0; kx < 7; kx++) {
                a0 += sw[ky * 7 + kx]      * smax[r + ky][cp + kx]
                    + sw[49 + ky * 7 + kx] * savg[r + ky][cp + kx];
            }
        }
        sgate[r][cp] = __saturatef((a0 + 3.0f) * (1.0f / 6.0f));
    }
    __syncthreads();

    // Broadcast multiply: thread = (channel-quarter, px4). Each thread streams
    // 64 channels of one float4 pixel. 256 threads = 4 quarters x 64 px4.
    int px4 = tid & 63;            // 0..63  (float4 pixel within 16x16 tile)
    int cq  = tid >> 6;            // 0..3
    int rr  = px4 >> 2;            // tile row (4 float4 per row)
    int cc4 = px4 & 3;             // float4 col within row

    float4 g = *reinterpret_cast<const float4*>(&sgate[rr][cc4 * 4]);

    const size_t plane4 = HWn / 4;
    int prow4 = ((h0 + rr) * Wn + w0 + cc4 * 4) >> 2;
    const float4* xin = reinterpret_cast<const float4*>(x) +
                        (size_t)b * Cn * plane4 + (size_t)cq * 64 * plane4 + prow4;
    float4* xout = reinterpret_cast<float4*>(out) +
                   (size_t)b * Cn * plane4 + (size_t)cq * 64 * plane4 + prow4;

#pragma unroll 8
    for (int c = 0; c < 64; c++) {
        float4 v = __ldcs(xin + (size_t)c * plane4);
        v.x *= g.x; v.y *= g.y; v.z *= g.z; v.w *= g.w;
        __stcs(xout + (size_t)c * plane4, v);
    }
}

extern "C" void kernel_launch(void* const* d_in, const int* in_sizes, int n_in,
                              void* d_out, int out_size) {
    const float* x  = (const float*)d_in[0];
    const float* cw = (const float*)d_in[1];
    const float* cb = (const float*)d_in[2];
    float* out = (float*)d_out;

    // 1024 blocks x 64 threads
    reduce_kernel<<<(Bn * HWn / 4) / 64, 64>>>(x);

    // 1024 blocks x 256 threads: grid (8, 8, 16)
    gate_mul_kernel<<<dim3(Wn / TW, Hn / TH, Bn), 256>>>(x, cw, cb, out);
}

// round 5
// speedup vs baseline: 1.0415x; 1.0415x over previous
#include <cuda_runtime.h>
#include <cuda_bf16.h>

// SpatialBlock: x[16,256,128,128] fp32
//   max_c(x), mean_c(x) -> conv7x7 (2->1, SAME zero pad) + bias -> hsigmoid -> x * gate
//
// R5: gate tile 32x8 -- keeps 128B-contiguous warp rows (R4's 16-wide tile
//     doubled L1tex wavefronts: L1 35->49%, DRAM 73->66%), AND 1024 blocks
//     (1% wave tail) AND ~55 warps/SM. Reduce unchanged from R4 (improved).

#define Bn 16
#define Cn 256
#define Hn 128
#define Wn 128
#define HWn (Hn * Wn)

__device__ float g_max[Bn * HWn];
__device__ float g_avg[Bn * HWn];

__global__ void __launch_bounds__(64)
reduce_kernel(const float* __restrict__ x) {
    int t = blockIdx.x * 64 + threadIdx.x;        // 0 .. B*HW/4 - 1
    int b = t / (HWn / 4);
    int p4 = t - b * (HWn / 4);

    const float4* xb = reinterpret_cast<const float4*>(x) +
                       (size_t)b * Cn * (HWn / 4) + p4;

    float4 v = __ldcs(xb);
    float4 mx = v;
    float4 sm = v;

#pragma unroll 16
    for (int c = 1; c < Cn; c++) {
        float4 u = __ldcs(xb + (size_t)c * (HWn / 4));
        mx.x = fmaxf(mx.x, u.x); mx.y = fmaxf(mx.y, u.y);
        mx.z = fmaxf(mx.z, u.z); mx.w = fmaxf(mx.w, u.w);
        sm.x += u.x; sm.y += u.y; sm.z += u.z; sm.w += u.w;
    }

    const float inv = 1.0f / (float)Cn;
    sm.x *= inv; sm.y *= inv; sm.z *= inv; sm.w *= inv;

    reinterpret_cast<float4*>(g_max)[(size_t)b * (HWn / 4) + p4] = mx;
    reinterpret_cast<float4*>(g_avg)[(size_t)b * (HWn / 4) + p4] = sm;
}

#define TW 32   // tile width  (pixels) -- 128B rows, full-line warp requests
#define TH 8    // tile height (pixels) -- 1024 blocks for wave balance

__global__ void __launch_bounds__(256)
gate_mul_kernel(const float* __restrict__ x,
                const float* __restrict__ cw,   // [1,2,7,7] = 98 floats
                const float* __restrict__ cb,   // [1]
                float* __restrict__ out) {
    __shared__ float sw[98];
    __shared__ float sbias;
    __shared__ __align__(16) float smax[TH + 6][TW + 6];
    __shared__ __align__(16) float savg[TH + 6][TW + 6];
    __shared__ __align__(16) float sgate[TH][TW];

    int tid = threadIdx.x;                        // 0..255
    if (tid < 98) sw[tid] = cw[tid];
    if (tid == 98) sbias = cb[0];

    int b  = blockIdx.z;
    int h0 = blockIdx.y * TH;
    int w0 = blockIdx.x * TW;

    const float* bmax = g_max + b * HWn;
    const float* bavg = g_avg + b * HWn;

    // Cooperative halo load (zero padding == conv SAME zero-pad). 14x38=532.
    for (int i = tid; i < (TH + 6) * (TW + 6); i += 256) {
        int r  = i / (TW + 6);
        int cc = i - r * (TW + 6);
        int hh = h0 + r - 3;
        int ww = w0 + cc - 3;
        float vm = 0.0f, va = 0.0f;
        if ((unsigned)hh < (unsigned)Hn && (unsigned)ww < (unsigned)Wn) {
            int gi = hh * Wn + ww;
            vm = bmax[gi];
            va = bavg[gi];
        }
        smax[r][cc] = vm;
        savg[r][cc] = va;
    }
    __syncthreads();

    // Conv + hsigmoid: 256 threads, one pixel each of the 32x8 tile
    {
        int r  = tid >> 5;         // 0..7
        int cp = tid & 31;         // 0..31
        float a0 = sbias;
#pragma unroll
        for (int ky = 0; ky < 7; ky++) {
#pragma unroll
            for (int kx = 0; kx < 7; kx++) {
                a0 += sw[ky * 7 + kx]      * smax[r + ky][cp + kx]
                    + sw[49 + ky * 7 + kx] * savg[r + ky][cp + kx];
            }
        }
        sgate[r][cp] = __saturatef((a0 + 3.0f) * (1.0f / 6.0f));
    }
    __syncthreads();

    // Broadcast multiply: thread = (channel-quarter, px4). 64 px4 in tile,
    // 4 quarters x 64 channels. Warp = 4 rows x 8 float4 = 128B/row.
    int px4 = tid & 63;            // 0..63
    int cq  = tid >> 6;            // 0..3
    int rr  = px4 >> 3;            // tile row 0..7
    int cc4 = px4 & 7;             // float4 col 0..7

    float4 g = *reinterpret_cast<const float4*>(&sgate[rr][cc4 * 4]);

    const size_t plane4 = HWn / 4;
    int prow4 = ((h0 + rr) * Wn + w0 + cc4 * 4) >> 2;
    const float4* xin = reinterpret_cast<const float4*>(x) +
                        (size_t)b * Cn * plane4 + (size_t)cq * 64 * plane4 + prow4;
    float4* xout = reinterpret_cast<float4*>(out) +
                   (size_t)b * Cn * plane4 + (size_t)cq * 64 * plane4 + prow4;

#pragma unroll 8
    for (int c = 0; c < 64; c++) {
        float4 v = __ldcs(xin + (size_t)c * plane4);
        v.x *= g.x; v.y *= g.y; v.z *= g.z; v.w *= g.w;
        __stcs(xout + (size_t)c * plane4, v);
    }
}

extern "C" void kernel_launch(void* const* d_in, const int* in_sizes, int n_in,
                              void* d_out, int out_size) {
    const float* x  = (const float*)d_in[0];
    const float* cw = (const float*)d_in[1];
    const float* cb = (const float*)d_in[2];
    float* out = (float*)d_out;

    // 1024 blocks x 64 threads
    reduce_kernel<<<(Bn * HWn / 4) / 64, 64>>>(x);

    // grid (4, 16, 16) = 1024 blocks x 256 threads
    gate_mul_kernel<<<dim3(Wn / TW, Hn / TH, Bn), 256>>>(x, cw, cb, out);
}

// round 6
// speedup vs baseline: 1.0793x; 1.0363x over previous
#include <cuda_runtime.h>
#include <cuda_bf16.h>

// SpatialBlock: x[16,256,128,128] fp32
//   max_c(x), mean_c(x) -> conv7x7 (2->1, SAME zero pad) + bias -> hsigmoid -> x * gate
//
// R6: reduce gets 2-way channel split (128 thr/block: 64 px4 x 2 channel
//     halves, shared-memory combine) -> 27.7 warps/SM instead of the
//     structurally-pinned 13.8. Gate_mul is at its mixed-stream HBM ceiling
//     (6.29 TB/s, flat across occ 40->80%) and is kept identical to R5.

#define Bn 16
#define Cn 256
#define Hn 128
#define Wn 128
#define HWn (Hn * Wn)

__device__ float g_max[Bn * HWn];
__device__ float g_avg[Bn * HWn];

#define RPX 64   // float4 pixels per reduce block

__global__ void __launch_bounds__(128)
reduce_kernel(const float* __restrict__ x) {
    __shared__ __align__(16) float4 smx[2][RPX];
    __shared__ __align__(16) float4 ssm[2][RPX];

    int px   = threadIdx.x & 63;          // 0..63: float4 pixel within block
    int half = threadIdx.x >> 6;          // 0 or 1: channel half

    int t  = blockIdx.x * RPX + px;       // global float4-pixel id
    int b  = t / (HWn / 4);
    int p4 = t - b * (HWn / 4);

    const float4* xb = reinterpret_cast<const float4*>(x) +
                       (size_t)b * Cn * (HWn / 4) +
                       (size_t)half * 128 * (HWn / 4) + p4;

    float4 v = __ldcs(xb);
    float4 mx = v;
    float4 sm = v;

#pragma unroll 16
    for (int c = 1; c < 128; c++) {
        float4 u = __ldcs(xb + (size_t)c * (HWn / 4));
        mx.x = fmaxf(mx.x, u.x); mx.y = fmaxf(mx.y, u.y);
        mx.z = fmaxf(mx.z, u.z); mx.w = fmaxf(mx.w, u.w);
        sm.x += u.x; sm.y += u.y; sm.z += u.z; sm.w += u.w;
    }

    smx[half][px] = mx;
    ssm[half][px] = sm;
    __syncthreads();

    if (threadIdx.x < RPX) {
        float4 m0 = smx[0][px], m1 = smx[1][px];
        float4 s0 = ssm[0][px], s1 = ssm[1][px];
        float4 mo, so;
        mo.x = fmaxf(m0.x, m1.x); mo.y = fmaxf(m0.y, m1.y);
        mo.z = fmaxf(m0.z, m1.z); mo.w = fmaxf(m0.w, m1.w);
        const float inv = 1.0f / (float)Cn;
        so.x = (s0.x + s1.x) * inv; so.y = (s0.y + s1.y) * inv;
        so.z = (s0.z + s1.z) * inv; so.w = (s0.w + s1.w) * inv;

        reinterpret_cast<float4*>(g_max)[(size_t)b * (HWn / 4) + p4] = mo;
        reinterpret_cast<float4*>(g_avg)[(size_t)b * (HWn / 4) + p4] = so;
    }
}

#define TW 32   // tile width  (pixels) -- 128B rows, full-line warp requests
#define TH 8    // tile height (pixels) -- 1024 blocks for wave balance

__global__ void __launch_bounds__(256)
gate_mul_kernel(const float* __restrict__ x,
                const float* __restrict__ cw,   // [1,2,7,7] = 98 floats
                const float* __restrict__ cb,   // [1]
                float* __restrict__ out) {
    __shared__ float sw[98];
    __shared__ float sbias;
    __shared__ __align__(16) float smax[TH + 6][TW + 6];
    __shared__ __align__(16) float savg[TH + 6][TW + 6];
    __shared__ __align__(16) float sgate[TH][TW];

    int tid = threadIdx.x;                        // 0..255
    if (tid < 98) sw[tid] = cw[tid];
    if (tid == 98) sbias = cb[0];

    int b  = blockIdx.z;
    int h0 = blockIdx.y * TH;
    int w0 = blockIdx.x * TW;

    const float* bmax = g_max + b * HWn;
    const float* bavg = g_avg + b * HWn;

    // Cooperative halo load (zero padding == conv SAME zero-pad). 14x38=532.
    for (int i = tid; i < (TH + 6) * (TW + 6); i += 256) {
        int r  = i / (TW + 6);
        int cc = i - r * (TW + 6);
        int hh = h0 + r - 3;
        int ww = w0 + cc - 3;
        float vm = 0.0f, va = 0.0f;
        if ((unsigned)hh < (unsigned)Hn && (unsigned)ww < (unsigned)Wn) {
            int gi = hh * Wn + ww;
            vm = bmax[gi];
            va = bavg[gi];
        }
        smax[r][cc] = vm;
        savg[r][cc] = va;
    }
    __syncthreads();

    // Conv + hsigmoid: 256 threads, one pixel each of the 32x8 tile
    {
        int r  = tid >> 5;         // 0..7
        int cp = tid & 31;         // 0..31
        float a0 = sbias;
#pragma unroll
        for (int ky = 0; ky < 7; ky++) {
#pragma unroll
            for (int kx = 0; kx < 7; kx++) {
                a0 += sw[ky * 7 + kx]      * smax[r + ky][cp + kx]
                    + sw[49 + ky * 7 + kx] * savg[r + ky][cp + kx];
            }
        }
        sgate[r][cp] = __saturatef((a0 + 3.0f) * (1.0f / 6.0f));
    }
    __syncthreads();

    // Broadcast multiply: thread = (channel-quarter, px4). 64 px4 in tile,
    // 4 quarters x 64 channels. Warp = 4 rows x 8 float4 = 128B/row.
    int px4 = tid & 63;            // 0..63
    int cq  = tid >> 6;            // 0..3
    int rr  = px4 >> 3;            // tile row 0..7
    int cc4 = px4 & 7;             // float4 col 0..7

    float4 g = *reinterpret_cast<const float4*>(&sgate[rr][cc4 * 4]);

    const size_t plane4 = HWn / 4;
    int prow4 = ((h0 + rr) * Wn + w0 + cc4 * 4) >> 2;
    const float4* xin = reinterpret_cast<const float4*>(x) +
                        (size_t)b * Cn * plane4 + (size_t)cq * 64 * plane4 + prow4;
    float4* xout = reinterpret_cast<float4*>(out) +
                   (size_t)b * Cn * plane4 + (size_t)cq * 64 * plane4 + prow4;

#pragma unroll 8
    for (int c = 0; c < 64; c++) {
        float4 v = __ldcs(xin + (size_t)c * plane4);
        v.x *= g.x; v.y *= g.y; v.z *= g.z; v.w *= g.w;
        __stcs(xout + (size_t)c * plane4, v);
    }
}

extern "C" void kernel_launch(void* const* d_in, const int* in_sizes, int n_in,
                              void* d_out, int out_size) {
    const float* x  = (const float*)d_in[0];
    const float* cw = (const float*)d_in[1];
    const float* cb = (const float*)d_in[2];
    float* out = (float*)d_out;

    // 1024 blocks x 128 threads (64 px4 x 2 channel halves each)
    reduce_kernel<<<(Bn * HWn / 4) / RPX, 128>>>(x);

    // grid (4, 16, 16) = 1024 blocks x 256 threads
    gate_mul_kernel<<<dim3(Wn / TW, Hn / TH, Bn), 256>>>(x, cw, cb, out);
}